// round 17
// baseline (speedup 1.0000x reference)
#include <cuda_runtime.h>

#define NN    1024
#define KNB   16
#define CS    256
#define CZ    128
#define CG    16
#define NRBF  64
#define NPAIR 256    // KNB*KNB
#define NUPAIR 136   // unique pairs j<=k
#define NTHR  512

typedef unsigned long long ull;

__device__ float g_nl[NN * CG];
__device__ float g_nr[NN * CG];

struct alignas(16) Smem {
    float z[KNB * CZ];          // layernormed knn edge feats      8 KB
    float e2[KNB * CZ];         // sigmoid(zWeg+beg)*(zWep+bep)    8 KB
    float upd[KNB * CZ];        // triangle update accumulator     8 KB
    float aT[CG][KNB];          // nl[src] transposed              1 KB
    float bT[CG][KNB];          // nr[src] transposed              1 KB
    union {
        float rbfT[NRBF * NUPAIR];  // rbf[r][upair]              34 KB
        float T[KNB * CG * 32];     // T[(j*16+g2)*32+lane]       32 KB
    } u;
    float df[NPAIR * CZ];       // masked df[(j*16+k)*128 + c]   128 KB
    float tpos[KNB][4];
    float maskf[KNB];
    int   srcIdx[KNB];
    int   pj[NUPAIR];
    int   pk[NUPAIR];
};

__device__ __forceinline__ ull pk2(float x, float y) {
    ull r; asm("mov.b64 %0, {%1, %2};" : "=l"(r) : "f"(x), "f"(y)); return r;
}
__device__ __forceinline__ void upk2(float& x, float& y, ull v) {
    asm("mov.b64 {%0, %1}, %2;" : "=f"(x), "=f"(y) : "l"(v));
}
__device__ __forceinline__ ull ffma2(ull a, ull b, ull c) {
    ull d; asm("fma.rn.f32x2 %0, %1, %2, %3;" : "=l"(d) : "l"(a), "l"(b), "l"(c)); return d;
}

__device__ __forceinline__ float red32(float v) {
    v += __shfl_xor_sync(0xffffffffu, v, 16);
    v += __shfl_xor_sync(0xffffffffu, v, 8);
    v += __shfl_xor_sync(0xffffffffu, v, 4);
    v += __shfl_xor_sync(0xffffffffu, v, 2);
    v += __shfl_xor_sync(0xffffffffu, v, 1);
    return v;
}

__device__ __forceinline__ float sigmoidf_(float x) {
    return 1.0f / (1.0f + __expf(-x));
}

// ---------------------------------------------------------------------------
// Kernel 1: nl/nr = node_features @ {Wl,Wr} + {bl,br}
// ---------------------------------------------------------------------------
__global__ void nlnr_kernel(const float* __restrict__ nf,
                            const float* __restrict__ Wl, const float* __restrict__ bl,
                            const float* __restrict__ Wr, const float* __restrict__ br) {
    int idx = blockIdx.x * blockDim.x + threadIdx.x;
    int node = idx >> 4, g = idx & 15;
    const float* row = nf + node * CS;
    float al = bl[g], ar = br[g];
#pragma unroll 4
    for (int s = 0; s < CS; s++) {
        float v = __ldg(row + s);
        al = fmaf(v, Wl[s * CG + g], al);
        ar = fmaf(v, Wr[s * CG + g], ar);
    }
    g_nl[idx] = al;
    g_nr[idx] = ar;
}

// ---------------------------------------------------------------------------
// Kernel 2: fused TMU, one CTA per node, 512 threads (16 warps) for latency
// ---------------------------------------------------------------------------
__global__ void __launch_bounds__(NTHR, 1)
tmu_kernel(const float* __restrict__ ef,    const float* __restrict__ trans,
           const float* __restrict__ ln_g,  const float* __restrict__ ln_b,
           const float* __restrict__ Wep,   const float* __restrict__ bep,
           const float* __restrict__ Weg,   const float* __restrict__ beg,
           const float* __restrict__ Wdg,   const float* __restrict__ bdg,
           const float* __restrict__ Wdp,   const float* __restrict__ bdp,
           const float* __restrict__ lno_g, const float* __restrict__ lno_b,
           const float* __restrict__ Wout,  const float* __restrict__ bout,
           const float* __restrict__ Wog,   const float* __restrict__ bog,
           const int* __restrict__ eidx,          // int32 words; dtype probed
           const unsigned char* __restrict__ rmask, // element stride probed
           float* __restrict__ out) {
    extern __shared__ unsigned char smraw[];
    Smem& sm = *reinterpret_cast<Smem*>(smraw);

    const int i    = blockIdx.x;
    const int tid  = threadIdx.x;
    const int lane = tid & 31;
    const int w    = tid >> 5;          // 0..15

    // --- init: src indices, mask, translations, unique-pair table ---
    if (tid < KNB) {
        int odd_or = 0;
#pragma unroll
        for (int q = 1; q < 32; q += 2) odd_or |= __ldg(eidx + q);
        int si;
        if (odd_or == 0) si = __ldg(eidx + 2 * (i * KNB + tid));  // int64 storage
        else             si = __ldg(eidx + (i * KNB + tid));      // int32 storage
        sm.srcIdx[tid] = si;

        int mb = rmask[1] | rmask[2] | rmask[3] | rmask[5] | rmask[6] | rmask[7];
        int m4 = rmask[4] | rmask[12] | rmask[20];
        int ms = mb ? 1 : (m4 ? 4 : 8);
        float mi = rmask[(size_t)i * ms] ? 1.0f : 0.0f;
        sm.maskf[tid] = (rmask[(size_t)si * ms] ? 1.0f : 0.0f) * mi;

        sm.tpos[tid][0] = trans[si * 3 + 0];
        sm.tpos[tid][1] = trans[si * 3 + 1];
        sm.tpos[tid][2] = trans[si * 3 + 2];
    }
    if (tid < NUPAIR) {
        int rem = tid, j = 0;
        while (rem >= KNB - j) { rem -= KNB - j; j++; }
        sm.pj[tid] = j;
        sm.pk[tid] = j + rem;
    }
    __syncthreads();

    // --- z = LayerNorm(edge feats): 32 threads/row, 4 ch each ---
    {
        int j = tid >> 5, l = tid & 31;
        const float* er = ef + ((size_t)(i * KNB + j)) * CZ + l * 4;
        float4 v = *(const float4*)er;
        float s = v.x + v.y + v.z + v.w;
        s = red32(s);
        float m = s * (1.0f / CZ);
        float d0 = v.x - m, d1 = v.y - m, d2 = v.z - m, d3 = v.w - m;
        float ss = fmaf(d0, d0, fmaf(d1, d1, fmaf(d2, d2, d3 * d3)));
        ss = red32(ss);
        float rs = rsqrtf(ss * (1.0f / CZ) + 1e-5f);
        int cb = l * 4;
        sm.z[j * CZ + cb + 0] = fmaf(d0 * rs, ln_g[cb + 0], ln_b[cb + 0]);
        sm.z[j * CZ + cb + 1] = fmaf(d1 * rs, ln_g[cb + 1], ln_b[cb + 1]);
        sm.z[j * CZ + cb + 2] = fmaf(d2 * rs, ln_g[cb + 2], ln_b[cb + 2]);
        sm.z[j * CZ + cb + 3] = fmaf(d3 * rs, ln_g[cb + 3], ln_b[cb + 3]);
    }

    // --- gather aT = nl[src]^T, bT = nr[src]^T (first 256 threads) ---
    if (tid < 256) {
        int j = tid >> 4, g = tid & 15;
        int s = sm.srcIdx[j];
        sm.aT[g][j] = g_nl[s * CG + g];
        sm.bT[g][j] = g_nr[s * CG + g];
    }

    // --- rbf table over unique pairs, r-dim split across two thread groups ---
    {
        int p = -1, r0 = 0;
        if (tid < NUPAIR)                          { p = tid;        r0 = 0;  }
        else if (tid >= 256 && tid < 256 + NUPAIR) { p = tid - 256;  r0 = 32; }
        if (p >= 0) {
            int j = sm.pj[p], k = sm.pk[p];
            float dx = sm.tpos[j][0] - sm.tpos[k][0] + 1e-8f;
            float dy = sm.tpos[j][1] - sm.tpos[k][1] + 1e-8f;
            float dz = sm.tpos[j][2] - sm.tpos[k][2] + 1e-8f;
            float d = sqrtf(fmaf(dx, dx, fmaf(dy, dy, dz * dz)));
            const float stepm = 20.0f / 63.0f;
            const float invs  = 64.0f / 20.0f;
#pragma unroll 8
            for (int r = 0; r < 32; r++) {
                float uu = (d - (float)(r0 + r) * stepm) * invs;
                sm.u.rbfT[(r0 + r) * NUPAIR + p] = __expf(-uu * uu);
            }
        }
    }
    __syncthreads();

    // --- df = (rbf @ Wdp + bdp) * pair mask; 4 groups x 9 quads; two r-passes
    //     keep wdp2[32] (64 regs) per pass so regs fit the 128/thread cap ---
    {
        const int c = tid & (CZ - 1);
        const int h = tid >> 7;            // 0..3
        const float bdpc = bdp[c];
        const ull bdp2 = pk2(bdpc, bdpc);
#pragma unroll 1
        for (int rh = 0; rh < 2; rh++) {
            ull wdp2[32];
#pragma unroll
            for (int r = 0; r < 32; r++) {
                float v = Wdp[(rh * 32 + r) * CZ + c];
                wdp2[r] = pk2(v, v);
            }
#pragma unroll 1
            for (int qq = 0; qq < 9; qq++) {
                int quad = h * 9 + qq;
                if (quad >= 34) break;
                int p0 = quad * 4;
                ull a01, a23;
                if (rh == 0) { a01 = bdp2; a23 = bdp2; }
                else {
                    int ja = sm.pj[p0],     ka = sm.pk[p0];
                    int jb = sm.pj[p0 + 1], kb = sm.pk[p0 + 1];
                    int jc = sm.pj[p0 + 2], kc = sm.pk[p0 + 2];
                    int jd = sm.pj[p0 + 3], kd = sm.pk[p0 + 3];
                    a01 = pk2(sm.df[(ja * KNB + ka) * CZ + c], sm.df[(jb * KNB + kb) * CZ + c]);
                    a23 = pk2(sm.df[(jc * KNB + kc) * CZ + c], sm.df[(jd * KNB + kd) * CZ + c]);
                }
#pragma unroll
                for (int r = 0; r < 32; r++) {
                    ulonglong2 rb = *(const ulonglong2*)&sm.u.rbfT[(rh * 32 + r) * NUPAIR + p0];
                    a01 = ffma2(rb.x, wdp2[r], a01);
                    a23 = ffma2(rb.y, wdp2[r], a23);
                }
                float d0, d1, d2, d3;
                upk2(d0, d1, a01); upk2(d2, d3, a23);
                float dv[4] = {d0, d1, d2, d3};
                if (rh == 0) {
#pragma unroll
                    for (int t = 0; t < 4; t++) {
                        int p = p0 + t;
                        sm.df[(sm.pj[p] * KNB + sm.pk[p]) * CZ + c] = dv[t];
                    }
                } else {
#pragma unroll
                    for (int t = 0; t < 4; t++) {
                        int p = p0 + t;
                        int j = sm.pj[p], k = sm.pk[p];
                        float val = dv[t] * (sm.maskf[j] * sm.maskf[k]);
                        sm.df[(j * KNB + k) * CZ + c] = val;
                        sm.df[(k * KNB + j) * CZ + c] = val;
                    }
                }
            }
        }
    }

    // --- e2 = sigmoid(z@Weg+beg) * (z@Wep+bep): 4 groups x 4 rows ---
    {
        int c  = tid & (CZ - 1);
        int jh = tid >> 7;   // 0..3 -> rows jh*4 .. jh*4+3
        float ag[4], ap[4];
        float bgc = beg[c], bpc = bep[c];
#pragma unroll
        for (int q = 0; q < 4; q++) { ag[q] = bgc; ap[q] = bpc; }
        for (int s = 0; s < CZ; s += 4) {
            float wg0 = Weg[(s + 0) * CZ + c], wg1 = Weg[(s + 1) * CZ + c];
            float wg2 = Weg[(s + 2) * CZ + c], wg3 = Weg[(s + 3) * CZ + c];
            float wp0 = Wep[(s + 0) * CZ + c], wp1 = Wep[(s + 1) * CZ + c];
            float wp2 = Wep[(s + 2) * CZ + c], wp3 = Wep[(s + 3) * CZ + c];
#pragma unroll
            for (int jj = 0; jj < 4; jj++) {
                const float4 z4 = *(const float4*)&sm.z[(jh * 4 + jj) * CZ + s];
                ag[jj] = fmaf(z4.x, wg0, fmaf(z4.y, wg1, fmaf(z4.z, wg2, fmaf(z4.w, wg3, ag[jj]))));
                ap[jj] = fmaf(z4.x, wp0, fmaf(z4.y, wp1, fmaf(z4.z, wp2, fmaf(z4.w, wp3, ap[jj]))));
            }
        }
#pragma unroll
        for (int jj = 0; jj < 4; jj++)
            sm.e2[(jh * 4 + jj) * CZ + c] = sigmoidf_(ag[jj]) * ap[jj];
    }
    __syncthreads();

    // --- main loop: 4 channel chunks of 32; 16 warps: warp = g2 / row ---
    for (int c0 = 0; c0 < CZ; c0 += 32) {
        const int c = c0 + lane;
        const float bdgc = bdg[c];

        // T build: warp w owns g2 = w
        {
            int g2 = w;
            ull wr2[CG];
#pragma unroll
            for (int g1 = 0; g1 < CG; g1++) {
                float v = Wdg[(g1 * CG + g2) * CZ + c];
                wr2[g1] = pk2(v, v);
            }
#pragma unroll
            for (int jp = 0; jp < 8; jp++) {
                ull t2 = 0ull;
#pragma unroll
                for (int g1 = 0; g1 < CG; g1++) {
                    ull a2 = *(const ull*)&sm.aT[g1][jp * 2];
                    t2 = ffma2(a2, wr2[g1], t2);
                }
                float tx, ty; upk2(tx, ty, t2);
                sm.u.T[((jp * 2 + 0) * CG + g2) * 32 + lane] = tx;
                sm.u.T[((jp * 2 + 1) * CG + g2) * 32 + lane] = ty;
            }
        }
        __syncthreads();

        // pair phase: warp w owns row j = w; lane owns channel c
        {
            int j = w;
            float treg[CG];
#pragma unroll
            for (int g2 = 0; g2 < CG; g2++) treg[g2] = sm.u.T[(j * CG + g2) * 32 + lane];

            ull bdg2 = pk2(bdgc, bdgc);
            ull ga[8];
#pragma unroll
            for (int q = 0; q < 8; q++) ga[q] = bdg2;
#pragma unroll
            for (int g2 = 0; g2 < CG; g2++) {
                ull tv2 = pk2(treg[g2], treg[g2]);
                const ulonglong2* bp = (const ulonglong2*)&sm.bT[g2][0];
                ulonglong2 q0 = bp[0], q1 = bp[1], q2 = bp[2], q3 = bp[3];
                ga[0] = ffma2(tv2, q0.x, ga[0]); ga[1] = ffma2(tv2, q0.y, ga[1]);
                ga[2] = ffma2(tv2, q1.x, ga[2]); ga[3] = ffma2(tv2, q1.y, ga[3]);
                ga[4] = ffma2(tv2, q2.x, ga[4]); ga[5] = ffma2(tv2, q2.y, ga[5]);
                ga[6] = ffma2(tv2, q3.x, ga[6]); ga[7] = ffma2(tv2, q3.y, ga[7]);
            }

            float acc = 0.0f;
#pragma unroll
            for (int kk = 0; kk < 8; kk++) {
                float gA, gB; upk2(gA, gB, ga[kk]);
                int k = kk * 2;
                float e3a = sigmoidf_(gA) * sm.df[(j * KNB + k) * CZ + c];
                float e3b = sigmoidf_(gB) * sm.df[(j * KNB + k + 1) * CZ + c];
                acc = fmaf(e3a, sm.e2[k * CZ + c], acc);
                acc = fmaf(e3b, sm.e2[(k + 1) * CZ + c], acc);
            }
            sm.upd[j * CZ + c] = acc;
        }
        __syncthreads();
    }

    // --- LN(upd) in place: 32 threads/row, 4 ch each ---
    {
        int j = tid >> 5, l = tid & 31;
        float* up = &sm.upd[j * CZ + l * 4];
        float4 v = *(float4*)up;
        float s = v.x + v.y + v.z + v.w;
        s = red32(s);
        float m = s * (1.0f / CZ);
        float d0 = v.x - m, d1 = v.y - m, d2 = v.z - m, d3 = v.w - m;
        float ss = fmaf(d0, d0, fmaf(d1, d1, fmaf(d2, d2, d3 * d3)));
        ss = red32(ss);
        float rs = rsqrtf(ss * (1.0f / CZ) + 1e-5f);
        int cb = l * 4;
        up[0] = fmaf(d0 * rs, lno_g[cb + 0], lno_b[cb + 0]);
        up[1] = fmaf(d1 * rs, lno_g[cb + 1], lno_b[cb + 1]);
        up[2] = fmaf(d2 * rs, lno_g[cb + 2], lno_b[cb + 2]);
        up[3] = fmaf(d3 * rs, lno_g[cb + 3], lno_b[cb + 3]);
    }
    __syncthreads();

    // --- final: (LN(upd)@Wout+bout) * sigmoid(z@Wog+bog) * mask -> out ---
    {
        int c  = tid & (CZ - 1);
        int jh = tid >> 7;   // 0..3 -> rows jh*4 .. jh*4+3
        float ao[4], ag[4];
        float boc = bout[c], bgc = bog[c];
#pragma unroll
        for (int q = 0; q < 4; q++) { ao[q] = boc; ag[q] = bgc; }
        for (int s = 0; s < CZ; s += 4) {
            float wo0 = Wout[(s + 0) * CZ + c], wo1 = Wout[(s + 1) * CZ + c];
            float wo2 = Wout[(s + 2) * CZ + c], wo3 = Wout[(s + 3) * CZ + c];
            float wg0 = Wog[(s + 0) * CZ + c],  wg1 = Wog[(s + 1) * CZ + c];
            float wg2 = Wog[(s + 2) * CZ + c],  wg3 = Wog[(s + 3) * CZ + c];
#pragma unroll
            for (int jj = 0; jj < 4; jj++) {
                const float4 u4 = *(const float4*)&sm.upd[(jh * 4 + jj) * CZ + s];
                const float4 z4 = *(const float4*)&sm.z[(jh * 4 + jj) * CZ + s];
                ao[jj] = fmaf(u4.x, wo0, fmaf(u4.y, wo1, fmaf(u4.z, wo2, fmaf(u4.w, wo3, ao[jj]))));
                ag[jj] = fmaf(z4.x, wg0, fmaf(z4.y, wg1, fmaf(z4.z, wg2, fmaf(z4.w, wg3, ag[jj]))));
            }
        }
#pragma unroll
        for (int jj = 0; jj < 4; jj++) {
            int j = jh * 4 + jj;
            float val = ao[jj] * sigmoidf_(ag[jj]) * sm.maskf[j];
            out[((size_t)(i * KNB + j)) * CZ + c] = val;
        }
    }
}

// ---------------------------------------------------------------------------
extern "C" void kernel_launch(void* const* d_in, const int* in_sizes, int n_in,
                              void* d_out, int out_size) {
    const float*     nf    = (const float*)d_in[0];
    const float*     trans = (const float*)d_in[1];
    const float*     ef    = (const float*)d_in[2];
    const float*     ln_g  = (const float*)d_in[3];
    const float*     ln_b  = (const float*)d_in[4];
    const float*     Wl    = (const float*)d_in[5];
    const float*     bl    = (const float*)d_in[6];
    const float*     Wr    = (const float*)d_in[7];
    const float*     br    = (const float*)d_in[8];
    const float*     Wep   = (const float*)d_in[9];
    const float*     bep   = (const float*)d_in[10];
    const float*     Weg   = (const float*)d_in[11];
    const float*     beg   = (const float*)d_in[12];
    const float*     Wdg   = (const float*)d_in[13];
    const float*     bdg   = (const float*)d_in[14];
    const float*     Wdp   = (const float*)d_in[15];
    const float*     bdp   = (const float*)d_in[16];
    const float*     lno_g = (const float*)d_in[17];
    const float*     lno_b = (const float*)d_in[18];
    const float*     Wout  = (const float*)d_in[19];
    const float*     bout  = (const float*)d_in[20];
    const float*     Wog   = (const float*)d_in[21];
    const float*     bog   = (const float*)d_in[22];
    const int*       eidx  = (const int*)d_in[23];   // width auto-detected
    const unsigned char* rmask = (const unsigned char*)d_in[25]; // stride auto-detected
    float* out = (float*)d_out;

    cudaFuncSetAttribute(tmu_kernel, cudaFuncAttributeMaxDynamicSharedMemorySize,
                         (int)sizeof(Smem));

    nlnr_kernel<<<(NN * CG) / 256, 256>>>(nf, Wl, bl, Wr, br);

    tmu_kernel<<<NN, NTHR, sizeof(Smem)>>>(ef, trans, ln_g, ln_b,
                                           Wep, bep, Weg, beg, Wdg, bdg, Wdp, bdp,
                                           lno_g, lno_b, Wout, bout, Wog, bog,
                                           eidx, rmask, out);
}